// round 1
// baseline (speedup 1.0000x reference)
#include <cuda_runtime.h>
#include <cuda_bf16.h>

// ---------------------------------------------------------------------------
// 2D DCT-II as two batched GEMMs.
//   C[p,m] = cos(pi*(2m+1)*p/1024)   (M == N == 512, so Cp == Cq == C)
//   T[b]   = X[b] @ C^T
//   Y[b]   = scale .* (C @ T[b]),  scale = (2/512)*(p==0?1/sqrt2:1)*(q==0?1/sqrt2:1)
// ---------------------------------------------------------------------------

#define DCT_N   512
#define BATCH   128

__device__ float g_C [DCT_N * DCT_N];   // C  row-major [p][m]
__device__ float g_Ct[DCT_N * DCT_N];   // C^T row-major [n][q]
__device__ float g_T [BATCH * DCT_N * DCT_N]; // scratch (134 MB)

__global__ void init_tables_kernel() {
    int idx = blockIdx.x * blockDim.x + threadIdx.x;
    if (idx >= DCT_N * DCT_N) return;
    int p = idx >> 9;
    int m = idx & 511;
    // cos(pi * (2m+1)*p / 1024) computed with cospif for good argument reduction
    float v = cospif(((2.0f * (float)m + 1.0f) * (float)p) * (1.0f / 1024.0f));
    g_C [p * DCT_N + m] = v;
    g_Ct[m * DCT_N + p] = v;
}

// ---------------------------------------------------------------------------
// Classic 128x128x8 register-blocked SGEMM, A row-major MxK, B row-major KxN.
// Each of 256 threads computes an 8x8 micro-tile.
// MODE: 0 = A batched (img), B = g_Ct, out = g_T          (pass A)
//       1 = A = g_C, B batched (g_T), out batched, scaled  (pass B)
// ---------------------------------------------------------------------------

#define BM 128
#define BN 128
#define BK 8
#define TM 8
#define TN 8

template <int MODE>
__global__ __launch_bounds__(256)
void sgemm_dct_kernel(const float* __restrict__ img, float* __restrict__ out)
{
    const int K = DCT_N, N = DCT_N;
    const int b = blockIdx.z;

    const float* A;
    const float* B;
    float* C;
    if (MODE == 0) {
        A = img + (long)b * DCT_N * DCT_N;
        B = g_Ct;
        C = g_T + (long)b * DCT_N * DCT_N;
    } else {
        A = g_C;
        B = g_T + (long)b * DCT_N * DCT_N;
        C = out + (long)b * DCT_N * DCT_N;
    }

    __shared__ float As[BK][BM];
    __shared__ float Bs[BK][BN];

    const int tid  = threadIdx.x;          // 0..255
    const int rowC = blockIdx.y * BM;
    const int colC = blockIdx.x * BN;

    const int tx = tid & 15;               // 0..15 (col group)
    const int ty = tid >> 4;               // 0..15 (row group)

    // A tile load: BM x BK = 128x8 floats = 256 float4, one per thread
    const int aRow  = tid >> 1;            // 0..127
    const int aCol4 = (tid & 1) * 4;       // 0 or 4
    // B tile load: BK x BN = 8x128 floats = 256 float4, one per thread
    const int bRow  = tid >> 5;            // 0..7
    const int bCol4 = (tid & 31) * 4;      // 0..124

    const float* Aptr = A + (long)(rowC + aRow) * K + aCol4;
    const float* Bptr = B + (long)bRow * N + colC + bCol4;

    float acc[TM][TN];
    #pragma unroll
    for (int i = 0; i < TM; ++i)
        #pragma unroll
        for (int j = 0; j < TN; ++j)
            acc[i][j] = 0.0f;

    for (int k0 = 0; k0 < K; k0 += BK) {
        float4 av = *(const float4*)Aptr;
        float4 bv = *(const float4*)Bptr;

        // store A transposed so inner loop reads along M contiguously
        As[aCol4 + 0][aRow] = av.x;
        As[aCol4 + 1][aRow] = av.y;
        As[aCol4 + 2][aRow] = av.z;
        As[aCol4 + 3][aRow] = av.w;
        *(float4*)&Bs[bRow][bCol4] = bv;
        __syncthreads();

        #pragma unroll
        for (int kk = 0; kk < BK; ++kk) {
            float ar[TM], br[TN];
            // vectorized shared loads (LDS.128)
            float4 a0 = *(const float4*)&As[kk][ty * TM];
            float4 a1 = *(const float4*)&As[kk][ty * TM + 4];
            float4 b0 = *(const float4*)&Bs[kk][tx * TN];
            float4 b1 = *(const float4*)&Bs[kk][tx * TN + 4];
            ar[0]=a0.x; ar[1]=a0.y; ar[2]=a0.z; ar[3]=a0.w;
            ar[4]=a1.x; ar[5]=a1.y; ar[6]=a1.z; ar[7]=a1.w;
            br[0]=b0.x; br[1]=b0.y; br[2]=b0.z; br[3]=b0.w;
            br[4]=b1.x; br[5]=b1.y; br[6]=b1.z; br[7]=b1.w;

            #pragma unroll
            for (int i = 0; i < TM; ++i)
                #pragma unroll
                for (int j = 0; j < TN; ++j)
                    acc[i][j] += ar[i] * br[j];
        }
        __syncthreads();

        Aptr += BK;
        Bptr += (long)BK * N;
    }

    const float inv_sqrt2 = 0.70710678118654752440f;
    #pragma unroll
    for (int i = 0; i < TM; ++i) {
        int p = rowC + ty * TM + i;
        float rs = 1.0f;
        if (MODE == 1) {
            rs = 2.0f / (float)DCT_N;
            if (p == 0) rs *= inv_sqrt2;
        }
        #pragma unroll
        for (int j = 0; j < TN; j += 4) {
            int q = colC + tx * TN + j;
            float4 v;
            v.x = acc[i][j + 0];
            v.y = acc[i][j + 1];
            v.z = acc[i][j + 2];
            v.w = acc[i][j + 3];
            if (MODE == 1) {
                v.x *= rs; v.y *= rs; v.z *= rs; v.w *= rs;
                if (q == 0) v.x *= inv_sqrt2;   // q==0 column extra 1/sqrt2
            }
            *(float4*)&C[(long)p * N + q] = v;
        }
    }
}

extern "C" void kernel_launch(void* const* d_in, const int* in_sizes, int n_in,
                              void* d_out, int out_size)
{
    const float* img = (const float*)d_in[0];
    float* out = (float*)d_out;

    // cos tables (cheap: 262k threads, regenerated every call — deterministic)
    init_tables_kernel<<<(DCT_N * DCT_N + 255) / 256, 256>>>();

    dim3 grid(DCT_N / BN, DCT_N / BM, BATCH);
    // Pass A: T[b] = X[b] @ C^T
    sgemm_dct_kernel<0><<<grid, 256>>>(img, out);
    // Pass B: Y[b] = scale .* (C @ T[b])
    sgemm_dct_kernel<1><<<grid, 256>>>(img, out);
}

// round 2
// speedup vs baseline: 3.0306x; 3.0306x over previous
#include <cuda_runtime.h>
#include <cuda_bf16.h>

// ---------------------------------------------------------------------------
// 2D DCT-II as two batched GEMMs on tensor cores (tf32 mma.sync).
//   C[p,m] = cos(pi*(2m+1)*p/1024)   (M == N == 512, so Cp == Cq == C)
//   T[b]   = X[b] @ C^T
//   Y[b]   = scale .* (C @ T[b])
// ---------------------------------------------------------------------------

#define DCT_N   512
#define BATCH   128

#define BM 128
#define BN 128
#define BK 16
#define APITCH (BK + 4)    // 20 words: fragment loads bank-conflict-free
#define BPITCH (BN + 8)    // 136 words: fragment loads bank-conflict-free

__device__ float g_C [DCT_N * DCT_N];          // C   [p][m]
__device__ float g_Ct[DCT_N * DCT_N];          // C^T [m][p]
__device__ float g_T [BATCH * DCT_N * DCT_N];  // scratch

__global__ void init_tables_kernel() {
    int idx = blockIdx.x * blockDim.x + threadIdx.x;
    if (idx >= DCT_N * DCT_N) return;
    int p = idx >> 9;
    int m = idx & 511;
    float v = cospif(((2.0f * (float)m + 1.0f) * (float)p) * (1.0f / 1024.0f));
    g_C [p * DCT_N + m] = v;
    g_Ct[m * DCT_N + p] = v;
}

// round-to-nearest tf32 (keeps accuracy margin vs HW truncation)
__device__ __forceinline__ float tf32r(float x) {
    unsigned r;
    asm("cvt.rna.tf32.f32 %0, %1;" : "=r"(r) : "f"(x));
    return __uint_as_float(r);
}

__device__ __forceinline__ void mma_tf32(float c[4], unsigned a0, unsigned a1,
                                         unsigned a2, unsigned a3,
                                         unsigned b0, unsigned b1) {
    asm volatile(
        "mma.sync.aligned.m16n8k8.row.col.f32.tf32.tf32.f32 "
        "{%0,%1,%2,%3}, {%4,%5,%6,%7}, {%8,%9}, {%0,%1,%2,%3};\n"
        : "+f"(c[0]), "+f"(c[1]), "+f"(c[2]), "+f"(c[3])
        : "r"(a0), "r"(a1), "r"(a2), "r"(a3), "r"(b0), "r"(b1));
}

// MODE 0: A = img[b] (128x512 rows), B = g_Ct, out = g_T[b]
// MODE 1: A = g_C,                 B = g_T[b], out = d_out[b] (scaled)
template <int MODE>
__global__ __launch_bounds__(256, 2)
void gemm_tf32_dct(const float* __restrict__ img, float* __restrict__ out)
{
    const int b = blockIdx.z;
    const float* A;
    const float* B;
    float* Cout;
    if (MODE == 0) {
        A = img + (size_t)b * DCT_N * DCT_N;
        B = g_Ct;
        Cout = g_T + (size_t)b * DCT_N * DCT_N;
    } else {
        A = g_C;
        B = g_T + (size_t)b * DCT_N * DCT_N;
        Cout = out + (size_t)b * DCT_N * DCT_N;
    }

    __shared__ float As[2][BM * APITCH];
    __shared__ float Bs[2][BK * BPITCH];

    const int tid  = threadIdx.x;
    const int lane = tid & 31;
    const int warp = tid >> 5;
    const int grp  = lane >> 2;    // 0..7
    const int tig  = lane & 3;     // 0..3
    const int wm   = (warp & 1) * 64;   // warp m offset (2 warps in m)
    const int wn   = (warp >> 1) * 32;  // warp n offset (4 warps in n)

    const int rowC = blockIdx.y * BM;
    const int colC = blockIdx.x * BN;

    float4 aReg[2], bReg[2];

    // per-thread load coordinates (A: 128x16 = 512 float4, B: 16x128 = 512 float4)
    int aM[2], aK[2], bK[2], bN[2];
#pragma unroll
    for (int i = 0; i < 2; ++i) {
        int idx = tid + i * 256;
        aM[i] = idx >> 2;             // 0..127
        aK[i] = (idx & 3) * 4;        // 0,4,8,12
        bK[i] = idx >> 5;             // 0..15
        bN[i] = (idx & 31) * 4;       // 0..124
    }

    float acc[4][4][4];
#pragma unroll
    for (int mi = 0; mi < 4; ++mi)
#pragma unroll
        for (int ni = 0; ni < 4; ++ni)
#pragma unroll
            for (int r = 0; r < 4; ++r) acc[mi][ni][r] = 0.0f;

    // ---- prologue: tile 0 ----
#pragma unroll
    for (int i = 0; i < 2; ++i) {
        aReg[i] = *(const float4*)(A + (size_t)(rowC + aM[i]) * DCT_N + aK[i]);
        bReg[i] = *(const float4*)(B + (size_t)bK[i] * DCT_N + colC + bN[i]);
    }
#pragma unroll
    for (int i = 0; i < 2; ++i) {
        float4 av = make_float4(tf32r(aReg[i].x), tf32r(aReg[i].y),
                                tf32r(aReg[i].z), tf32r(aReg[i].w));
        *(float4*)&As[0][aM[i] * APITCH + aK[i]] = av;
        float4 bv = make_float4(tf32r(bReg[i].x), tf32r(bReg[i].y),
                                tf32r(bReg[i].z), tf32r(bReg[i].w));
        *(float4*)&Bs[0][bK[i] * BPITCH + bN[i]] = bv;
    }
    __syncthreads();

    const int NT = DCT_N / BK;   // 32 tiles
    for (int t = 0; t < NT; ++t) {
        // prefetch next tile into registers
        if (t < NT - 1) {
            int k0 = (t + 1) * BK;
#pragma unroll
            for (int i = 0; i < 2; ++i) {
                aReg[i] = *(const float4*)(A + (size_t)(rowC + aM[i]) * DCT_N + k0 + aK[i]);
                bReg[i] = *(const float4*)(B + (size_t)(k0 + bK[i]) * DCT_N + colC + bN[i]);
            }
        }

        // compute 2 k-steps (k=8 each) from current buffer
        const float* Ab = As[t & 1];
        const float* Bb = Bs[t & 1];
#pragma unroll
        for (int ks = 0; ks < 2; ++ks) {
            const int kb = ks * 8;
            unsigned af[4][4];
#pragma unroll
            for (int mi = 0; mi < 4; ++mi) {
                int m = wm + mi * 16 + grp;
                af[mi][0] = __float_as_uint(Ab[(m    ) * APITCH + kb + tig    ]);
                af[mi][1] = __float_as_uint(Ab[(m + 8) * APITCH + kb + tig    ]);
                af[mi][2] = __float_as_uint(Ab[(m    ) * APITCH + kb + tig + 4]);
                af[mi][3] = __float_as_uint(Ab[(m + 8) * APITCH + kb + tig + 4]);
            }
            unsigned bf[4][2];
#pragma unroll
            for (int ni = 0; ni < 4; ++ni) {
                int n = wn + ni * 8 + grp;
                bf[ni][0] = __float_as_uint(Bb[(kb + tig    ) * BPITCH + n]);
                bf[ni][1] = __float_as_uint(Bb[(kb + tig + 4) * BPITCH + n]);
            }
#pragma unroll
            for (int mi = 0; mi < 4; ++mi)
#pragma unroll
                for (int ni = 0; ni < 4; ++ni)
                    mma_tf32(acc[mi][ni], af[mi][0], af[mi][1], af[mi][2], af[mi][3],
                             bf[ni][0], bf[ni][1]);
        }
        __syncthreads();

        // store prefetched tile into the other buffer
        if (t < NT - 1) {
            int buf = (t + 1) & 1;
#pragma unroll
            for (int i = 0; i < 2; ++i) {
                float4 av = make_float4(tf32r(aReg[i].x), tf32r(aReg[i].y),
                                        tf32r(aReg[i].z), tf32r(aReg[i].w));
                *(float4*)&As[buf][aM[i] * APITCH + aK[i]] = av;
                float4 bv = make_float4(tf32r(bReg[i].x), tf32r(bReg[i].y),
                                        tf32r(bReg[i].z), tf32r(bReg[i].w));
                *(float4*)&Bs[buf][bK[i] * BPITCH + bN[i]] = bv;
            }
        }
        __syncthreads();
    }

    // ---- epilogue ----
    const float is2 = 0.70710678118654752440f;
#pragma unroll
    for (int mi = 0; mi < 4; ++mi) {
#pragma unroll
        for (int ni = 0; ni < 4; ++ni) {
            int q = colC + wn + ni * 8 + 2 * tig;
#pragma unroll
            for (int h = 0; h < 2; ++h) {
                int p = rowC + wm + mi * 16 + grp + h * 8;
                float v0 = acc[mi][ni][h * 2 + 0];
                float v1 = acc[mi][ni][h * 2 + 1];
                if (MODE == 1) {
                    float s = 2.0f / (float)DCT_N;
                    if (p == 0) s *= is2;
                    v0 *= s; v1 *= s;
                    if (q == 0) v0 *= is2;
                }
                *(float2*)&Cout[(size_t)p * DCT_N + q] = make_float2(v0, v1);
            }
        }
    }
}

extern "C" void kernel_launch(void* const* d_in, const int* in_sizes, int n_in,
                              void* d_out, int out_size)
{
    const float* img = (const float*)d_in[0];
    float* out = (float*)d_out;

    init_tables_kernel<<<(DCT_N * DCT_N + 255) / 256, 256>>>();

    dim3 grid(DCT_N / BN, DCT_N / BM, BATCH);
    gemm_tf32_dct<0><<<grid, 256>>>(img, out);
    gemm_tf32_dct<1><<<grid, 256>>>(img, out);
}

// round 4
// speedup vs baseline: 3.1802x; 1.0494x over previous
#include <cuda_runtime.h>
#include <cuda_bf16.h>
#include <cstdint>

// ---------------------------------------------------------------------------
// 2D DCT-II with one level of parity folding -> 4 half-K tf32 mma.sync GEMMs.
//   cos(pi*(2(511-n)+1)q/1024) = (-1)^q cos(pi*(2n+1)q/1024)
//   Pass A: T_t[2r+P][m] = sum_{n'<256} (X[m][n'] +- X[m][511-n']) * tblP[n'][r]
//   Pass B: Y[2r+P][q]   = scale * sum_{m'<256} (T_t[q][m'] +- T_t[q][511-m']) * tblP[m'][r]
// Both passes share one kernel shape: fold along contiguous dim, NT GEMM,
// transposing epilogue (output rows = 2r+P contiguous).
// ---------------------------------------------------------------------------

#define DCT_N 512
#define BATCH 128
#define KH    256      // folded K

#define BM 128
#define BN 128
#define BK 16
#define APITCH (BK + 4)    // 20
#define BPITCH (BN + 8)    // 136
#define SPITCH 65          // staging pitch (odd => conflict-free col reads)

#define AS_BYTES (BM * APITCH * 4)          // 10240
#define BS_BYTES (BK * BPITCH * 4)          // 8704
#define SMEM_BYTES (2*AS_BYTES + 2*BS_BYTES) // 37888 (> 128*65*4=33280 staging)

__device__ float g_BE[KH * KH];                      // [k'][r]: cos(pi(2k'+1)(2r)/1024)
__device__ float g_BO[KH * KH];                      // [k'][r]: cos(pi(2k'+1)(2r+1)/1024)
__device__ float g_T[(size_t)BATCH * DCT_N * DCT_N]; // T_t[b][q][m]

__global__ void init_tables_kernel() {
    int idx = blockIdx.x * blockDim.x + threadIdx.x;
    if (idx >= KH * KH) return;
    int k = idx >> 8;          // k' 0..255
    int r = idx & 255;         // r  0..255
    float a = 2.0f * (float)k + 1.0f;
    g_BE[idx] = cospif(a * (float)r * (1.0f / 512.0f));
    g_BO[idx] = cospif(a * (float)(2 * r + 1) * (1.0f / 1024.0f));
}

__device__ __forceinline__ float tf32r(float x) {
    unsigned r; asm("cvt.rna.tf32.f32 %0, %1;" : "=r"(r) : "f"(x));
    return __uint_as_float(r);
}

__device__ __forceinline__ void mma_tf32(float c[4], unsigned a0, unsigned a1,
                                         unsigned a2, unsigned a3,
                                         unsigned b0, unsigned b1) {
    asm volatile(
        "mma.sync.aligned.m16n8k8.row.col.f32.tf32.tf32.f32 "
        "{%0,%1,%2,%3}, {%4,%5,%6,%7}, {%8,%9}, {%0,%1,%2,%3};\n"
        : "+f"(c[0]), "+f"(c[1]), "+f"(c[2]), "+f"(c[3])
        : "r"(a0), "r"(a1), "r"(a2), "r"(a3), "r"(b0), "r"(b1));
}

// MODE 0: E = img[b],  O = g_T[b]   (no scale)
// MODE 1: E = g_T[b],  O = out[b]   (DCT scale)
template <int MODE>
__global__ __launch_bounds__(256, 2)
void dct_fold_gemm(const float* __restrict__ img, float* __restrict__ out)
{
    __shared__ __align__(16) char smem[SMEM_BYTES];
    float* Asb[2] = { (float*)(smem),            (float*)(smem + AS_BYTES) };
    float* Bsb[2] = { (float*)(smem + 2*AS_BYTES),
                      (float*)(smem + 2*AS_BYTES + BS_BYTES) };
    float* S = (float*)smem;   // epilogue staging (reuses As/Bs space)

    const int zc = blockIdx.z;
    const int b  = zc >> 1;
    const int P  = zc & 1;                 // output parity
    const float sgn = P ? -1.0f : 1.0f;

    const float* E = (MODE == 0 ? img : g_T) + (size_t)b * DCT_N * DCT_N;
    float*       O = (MODE == 0 ? g_T : out) + (size_t)b * DCT_N * DCT_N;
    const float* tbl = P ? g_BO : g_BE;

    const int iC = blockIdx.y * BM;        // rows of E / cols of output
    const int rC = blockIdx.x * BN;        // folded-index block

    const int tid  = threadIdx.x;
    const int lane = tid & 31;
    const int warp = tid >> 5;
    const int grp  = lane >> 2;
    const int tig  = lane & 3;
    const int wm   = (warp & 1) * 64;
    const int wn   = (warp >> 1) * 32;

    // per-thread load coords (A: 128x16 folded = 512 float4; B: 16x128 = 512 float4)
    int aM[2], aK[2], bK[2], bN[2];
#pragma unroll
    for (int i = 0; i < 2; ++i) {
        int idx = tid + i * 256;
        aM[i] = idx >> 2;
        aK[i] = (idx & 3) * 4;
        bK[i] = idx >> 5;
        bN[i] = (idx & 31) * 4;
    }
    const float* Af[2]; const float* Ar[2]; const float* Bp[2];
#pragma unroll
    for (int i = 0; i < 2; ++i) {
        Af[i] = E + (size_t)(iC + aM[i]) * DCT_N + aK[i];            // forward half
        Ar[i] = E + (size_t)(iC + aM[i]) * DCT_N + (508 - aK[i]);    // reversed half
        Bp[i] = tbl + (size_t)bK[i] * KH + rC + bN[i];
    }

    float acc[4][4][4];
#pragma unroll
    for (int mi = 0; mi < 4; ++mi)
#pragma unroll
        for (int ni = 0; ni < 4; ++ni)
#pragma unroll
            for (int r = 0; r < 4; ++r) acc[mi][ni][r] = 0.0f;

    float4 fReg[2], rReg[2], bReg[2];

    auto stage_store = [&](int buf) {
#pragma unroll
        for (int i = 0; i < 2; ++i) {
            float4 u;
            u.x = tf32r(fmaf(sgn, rReg[i].w, fReg[i].x));
            u.y = tf32r(fmaf(sgn, rReg[i].z, fReg[i].y));
            u.z = tf32r(fmaf(sgn, rReg[i].y, fReg[i].z));
            u.w = tf32r(fmaf(sgn, rReg[i].x, fReg[i].w));
            *(float4*)&Asb[buf][aM[i] * APITCH + aK[i]] = u;
            float4 bv = make_float4(tf32r(bReg[i].x), tf32r(bReg[i].y),
                                    tf32r(bReg[i].z), tf32r(bReg[i].w));
            *(float4*)&Bsb[buf][bK[i] * BPITCH + bN[i]] = bv;
        }
    };

    // prologue: tile 0
#pragma unroll
    for (int i = 0; i < 2; ++i) {
        fReg[i] = *(const float4*)Af[i];
        rReg[i] = *(const float4*)Ar[i];
        bReg[i] = *(const float4*)Bp[i];
        Af[i] += BK; Ar[i] -= BK; Bp[i] += (size_t)BK * KH;
    }
    stage_store(0);
    __syncthreads();

    const int NT = KH / BK;   // 16
    for (int t = 0; t < NT; ++t) {
        if (t < NT - 1) {
#pragma unroll
            for (int i = 0; i < 2; ++i) {
                fReg[i] = *(const float4*)Af[i];
                rReg[i] = *(const float4*)Ar[i];
                bReg[i] = *(const float4*)Bp[i];
                Af[i] += BK; Ar[i] -= BK; Bp[i] += (size_t)BK * KH;
            }
        }

        const float* Ab = Asb[t & 1];
        const float* Bb = Bsb[t & 1];
#pragma unroll
        for (int ks = 0; ks < 2; ++ks) {
            const int kb = ks * 8;
            unsigned af[4][4];
#pragma unroll
            for (int mi = 0; mi < 4; ++mi) {
                int m = wm + mi * 16 + grp;
                af[mi][0] = __float_as_uint(Ab[(m    ) * APITCH + kb + tig    ]);
                af[mi][1] = __float_as_uint(Ab[(m + 8) * APITCH + kb + tig    ]);
                af[mi][2] = __float_as_uint(Ab[(m    ) * APITCH + kb + tig + 4]);
                af[mi][3] = __float_as_uint(Ab[(m + 8) * APITCH + kb + tig + 4]);
            }
            unsigned bf[4][2];
#pragma unroll
            for (int ni = 0; ni < 4; ++ni) {
                int n = wn + ni * 8 + grp;
                bf[ni][0] = __float_as_uint(Bb[(kb + tig    ) * BPITCH + n]);
                bf[ni][1] = __float_as_uint(Bb[(kb + tig + 4) * BPITCH + n]);
            }
#pragma unroll
            for (int mi = 0; mi < 4; ++mi)
#pragma unroll
                for (int ni = 0; ni < 4; ++ni)
                    mma_tf32(acc[mi][ni], af[mi][0], af[mi][1], af[mi][2], af[mi][3],
                             bf[ni][0], bf[ni][1]);
        }
        __syncthreads();

        if (t < NT - 1) {
            stage_store((t + 1) & 1);
        }
        __syncthreads();
    }

    // ---- transposing epilogue: two 128x64 chunks staged in SMEM ----
    const float is2 = 0.70710678118654752440f;
#pragma unroll 1
    for (int cb = 0; cb < 2; ++cb) {
        if ((warp >> 2) == cb) {     // warps whose wn lies in [64*cb, 64*cb+64)
#pragma unroll
            for (int mi = 0; mi < 4; ++mi)
#pragma unroll
                for (int ni = 0; ni < 4; ++ni)
#pragma unroll
                    for (int h = 0; h < 2; ++h) {
                        int i  = wm + mi * 16 + grp + h * 8;
                        int rl = wn - cb * 64 + ni * 8 + 2 * tig;
                        S[i * SPITCH + rl    ] = acc[mi][ni][h * 2 + 0];
                        S[i * SPITCH + rl + 1] = acc[mi][ni][h * 2 + 1];
                    }
        }
        __syncthreads();
#pragma unroll
        for (int it = 0; it < 32; ++it) {
            int idx = it * 256 + tid;
            int rl  = idx >> 7;           // 0..63
            int i   = idx & 127;          // 0..127
            int rg  = rC + cb * 64 + rl;
            int prow = 2 * rg + P;
            float v = S[i * SPITCH + rl];
            if (MODE == 1) {
                float sc = 2.0f / (float)DCT_N;
                if (prow == 0) sc *= is2;
                v *= sc;
                if (iC + i == 0) v *= is2;
            }
            O[(size_t)prow * DCT_N + iC + i] = v;
        }
        __syncthreads();
    }
}

extern "C" void kernel_launch(void* const* d_in, const int* in_sizes, int n_in,
                              void* d_out, int out_size)
{
    const float* img = (const float*)d_in[0];
    float* out = (float*)d_out;

    init_tables_kernel<<<(KH * KH + 255) / 256, 256>>>();

    dim3 grid(KH / BN, DCT_N / BM, BATCH * 2);   // (2, 4, 256)
    dct_fold_gemm<0><<<grid, 256>>>(img, out);
    dct_fold_gemm<1><<<grid, 256>>>(img, out);
}

// round 5
// speedup vs baseline: 8.6957x; 2.7343x over previous
#include <cuda_runtime.h>
#include <cuda_fp16.h>
#include <cstdint>

// ---------------------------------------------------------------------------
// 2D DCT-II with parity folding, fp16 mma.sync (m16n8k16, fp32 accum).
//   Pass A: T_t[2r+P][m] = sum_{n'<256} fold_P(X[m])[n'] * tblP[n'][r]
//   Pass B: Y[2r+P][q]   = scale * sum_{m'<256} fold_P(T_t[q])[m'] * tblP[m'][r]
// fold_P(x)[k] = x[k] + (P?-1:+1)*x[511-k]
// ---------------------------------------------------------------------------

#define DCT_N 512
#define BATCH 128
#define KH    256
#define BM    128
#define BN    128
#define BK    32
#define NT    (KH / BK)      // 8
#define APH   40             // A smem pitch (halfs)
#define BPH   136            // B smem pitch (halfs)
#define SPH   136            // mode-0 staging pitch (halfs)
#define SPF   132            // mode-1 staging pitch (floats)

#define OFF_A0 0
#define OFF_A1 10240
#define OFF_B0 20480
#define OFF_B1 29184
#define SMEM_BYTES 37888

__device__ __align__(16) __half g_BE[KH * KH];   // [k'][r] cos(pi(2k'+1)(2r)/1024)
__device__ __align__(16) __half g_BO[KH * KH];   // [k'][r] cos(pi(2k'+1)(2r+1)/1024)
__device__ __align__(16) __half g_T[(size_t)BATCH * DCT_N * DCT_N];  // T_t[b][q][m]

__global__ void init_tables_kernel() {
    int idx = blockIdx.x * blockDim.x + threadIdx.x;
    if (idx >= KH * KH) return;
    int k = idx >> 8, r = idx & 255;
    float a = 2.0f * (float)k + 1.0f;
    g_BE[idx] = __float2half_rn(cospif(a * (float)r * (1.0f / 512.0f)));
    g_BO[idx] = __float2half_rn(cospif(a * (float)(2 * r + 1) * (1.0f / 1024.0f)));
}

__device__ __forceinline__ uint32_t smem_u32(const void* p) {
    uint32_t a;
    asm("{ .reg .u64 t; cvta.to.shared.u64 t, %1; cvt.u32.u64 %0, t; }" : "=r"(a) : "l"(p));
    return a;
}
__device__ __forceinline__ void cp16(uint32_t dst, const void* src) {
    asm volatile("cp.async.cg.shared.global [%0], [%1], 16;" :: "r"(dst), "l"(src));
}
#define CP_COMMIT() asm volatile("cp.async.commit_group;" ::: "memory")
#define CP_WAIT(n)  asm volatile("cp.async.wait_group %0;" :: "n"(n) : "memory")

__device__ __forceinline__ void ldsm4(uint32_t r[4], uint32_t addr) {
    asm volatile("ldmatrix.sync.aligned.m8n8.x4.shared.b16 {%0,%1,%2,%3}, [%4];"
                 : "=r"(r[0]), "=r"(r[1]), "=r"(r[2]), "=r"(r[3]) : "r"(addr));
}
__device__ __forceinline__ void ldsm4t(uint32_t r[4], uint32_t addr) {
    asm volatile("ldmatrix.sync.aligned.m8n8.x4.trans.shared.b16 {%0,%1,%2,%3}, [%4];"
                 : "=r"(r[0]), "=r"(r[1]), "=r"(r[2]), "=r"(r[3]) : "r"(addr));
}
__device__ __forceinline__ void mma_f16(float c[4], const uint32_t a[4],
                                        uint32_t b0, uint32_t b1) {
    asm volatile(
        "mma.sync.aligned.m16n8k16.row.col.f32.f16.f16.f32 "
        "{%0,%1,%2,%3},{%4,%5,%6,%7},{%8,%9},{%0,%1,%2,%3};"
        : "+f"(c[0]), "+f"(c[1]), "+f"(c[2]), "+f"(c[3])
        : "r"(a[0]), "r"(a[1]), "r"(a[2]), "r"(a[3]), "r"(b0), "r"(b1));
}
__device__ __forceinline__ uint32_t packh2(float lo, float hi) {
    __half2 h = __floats2half2_rn(lo, hi);
    return *(uint32_t*)&h;
}

// MODE 0: A-source = img (fp32), output = g_T (fp16), no scale
// MODE 1: A-source = g_T (fp16), output = d_out (fp32), DCT scale
template <int MODE>
__global__ __launch_bounds__(256, 2)
void dct_fold_fp16(const float* __restrict__ img, float* __restrict__ out)
{
    __shared__ __align__(16) char smem[SMEM_BYTES];
    const uint32_t sb = smem_u32(smem);

    const int tid = threadIdx.x, lane = tid & 31, warp = tid >> 5;
    const int zc = blockIdx.z, b = zc >> 1, P = zc & 1;
    const float sgn = P ? -1.0f : 1.0f;
    const int iC = blockIdx.y * BM;
    const int rC = blockIdx.x * BN;
    const int wm = (warp & 1) * 64, wn = (warp >> 1) * 32;
    const int grp = lane >> 2, tig = lane & 3;

    const __half* tbl = P ? g_BO : g_BE;
    const float* Ef = img + (size_t)b * DCT_N * DCT_N;
    const __half* Eh = g_T + (size_t)b * DCT_N * DCT_N;
    __half* Oh = g_T + (size_t)b * DCT_N * DCT_N;
    float*  Of = out + (size_t)b * DCT_N * DCT_N;

    // loader coordinates
    int rowA[2], kh[2], rowB[2], nB[2];
#pragma unroll
    for (int i = 0; i < 2; ++i) {
        int g = tid + i * 256;
        rowA[i] = g >> 2;  kh[i] = (g & 3) * 8;    // A: 128 rows x 4 granules
        rowB[i] = g >> 4;  nB[i] = (g & 15) * 8;   // B: 32 rows x 16 granules
    }

    // fragment lane byte offsets (relative to buffer base)
    const int aLaneOff =
        (((wm + (lane & 7) + ((lane >> 3) & 1) * 8) * APH) + ((lane >> 4) * 8)) * 2;
    const int bLaneOff =
        ((((((lane >> 4) & 1) * 8) + (lane & 7)) * BPH) + (((lane >> 3) & 1) * 8)) * 2;

    float acc[4][4][4];
#pragma unroll
    for (int mi = 0; mi < 4; ++mi)
#pragma unroll
        for (int ni = 0; ni < 4; ++ni)
#pragma unroll
            for (int r = 0; r < 4; ++r) acc[mi][ni][r] = 0.0f;

    uint4 oReg[2];   // folded + packed A granules (8 halfs each)

    auto ldA = [&](int t) {
#pragma unroll
        for (int i = 0; i < 2; ++i) {
            int kp = t * BK + kh[i];
            if (MODE == 0) {
                const float* base = Ef + (size_t)(iC + rowA[i]) * DCT_N;
                float4 F0 = *(const float4*)(base + kp);
                float4 F1 = *(const float4*)(base + kp + 4);
                float4 R1 = *(const float4*)(base + 508 - kp);  // rev of j0..3
                float4 R0 = *(const float4*)(base + 504 - kp);  // rev of j4..7
                oReg[i].x = packh2(fmaf(sgn, R1.w, F0.x), fmaf(sgn, R1.z, F0.y));
                oReg[i].y = packh2(fmaf(sgn, R1.y, F0.z), fmaf(sgn, R1.x, F0.w));
                oReg[i].z = packh2(fmaf(sgn, R0.w, F1.x), fmaf(sgn, R0.z, F1.y));
                oReg[i].w = packh2(fmaf(sgn, R0.y, F1.z), fmaf(sgn, R0.x, F1.w));
            } else {
                const __half* base = Eh + (size_t)(iC + rowA[i]) * DCT_N;
                uint4 F = *(const uint4*)(base + kp);
                uint4 R = *(const uint4*)(base + 504 - kp);
                __half2 f0 = *(__half2*)&F.x, f1 = *(__half2*)&F.y;
                __half2 f2 = *(__half2*)&F.z, f3 = *(__half2*)&F.w;
                __half2 r0 = __lowhigh2highlow(*(__half2*)&R.w);
                __half2 r1 = __lowhigh2highlow(*(__half2*)&R.z);
                __half2 r2 = __lowhigh2highlow(*(__half2*)&R.y);
                __half2 r3 = __lowhigh2highlow(*(__half2*)&R.x);
                __half2 o0 = P ? __hsub2(f0, r0) : __hadd2(f0, r0);
                __half2 o1 = P ? __hsub2(f1, r1) : __hadd2(f1, r1);
                __half2 o2 = P ? __hsub2(f2, r2) : __hadd2(f2, r2);
                __half2 o3 = P ? __hsub2(f3, r3) : __hadd2(f3, r3);
                oReg[i].x = *(uint32_t*)&o0; oReg[i].y = *(uint32_t*)&o1;
                oReg[i].z = *(uint32_t*)&o2; oReg[i].w = *(uint32_t*)&o3;
            }
        }
    };
    auto stsA = [&](int bufOff) {
#pragma unroll
        for (int i = 0; i < 2; ++i)
            *(uint4*)(smem + bufOff + (rowA[i] * APH + kh[i]) * 2) = oReg[i];
    };
    auto cpB = [&](int t, int bufOff) {
#pragma unroll
        for (int i = 0; i < 2; ++i) {
            uint32_t dst = sb + bufOff + (rowB[i] * BPH + nB[i]) * 2;
            const __half* src = tbl + (size_t)(t * BK + rowB[i]) * KH + rC + nB[i];
            cp16(dst, src);
        }
        CP_COMMIT();
    };
    auto compute = [&](int aOff, int bOff) {
#pragma unroll
        for (int ks = 0; ks < 2; ++ks) {
            uint32_t a[4][4];
#pragma unroll
            for (int mi = 0; mi < 4; ++mi)
                ldsm4(a[mi], sb + aOff + aLaneOff + mi * (16 * APH * 2) + ks * 32);
            uint32_t bq[2][4];
#pragma unroll
            for (int pr = 0; pr < 2; ++pr)
                ldsm4t(bq[pr], sb + bOff + bLaneOff + ks * (16 * BPH * 2)
                               + (wn + pr * 16) * 2);
#pragma unroll
            for (int mi = 0; mi < 4; ++mi)
#pragma unroll
                for (int ni = 0; ni < 4; ++ni)
                    mma_f16(acc[mi][ni], a[mi],
                            bq[ni >> 1][ni & 1], bq[ni >> 1][2 + (ni & 1)]);
        }
    };

    const int aOffs[2] = { OFF_A0, OFF_A1 };
    const int bOffs[2] = { OFF_B0, OFF_B1 };

    // prologue
    ldA(0); cpB(0, bOffs[0]);
    stsA(aOffs[0]);
    ldA(1); cpB(1, bOffs[1]);
    CP_WAIT(1);
    __syncthreads();

    for (int t = 0; t < NT; ++t) {
        compute(aOffs[t & 1], bOffs[t & 1]);
        __syncthreads();
        if (t + 1 < NT) stsA(aOffs[(t + 1) & 1]);
        if (t + 2 < NT) { ldA(t + 2); cpB(t + 2, bOffs[t & 1]); }
        if (t + 1 < NT) {
            if (t + 2 < NT) { CP_WAIT(1); } else { CP_WAIT(0); }
            __syncthreads();
        }
    }

    // ---------------- epilogue ----------------
    const float is2 = 0.70710678118654752440f;
    if (MODE == 0) {
        __half* Sh = (__half*)smem;
#pragma unroll
        for (int mi = 0; mi < 4; ++mi)
#pragma unroll
            for (int ni = 0; ni < 4; ++ni)
#pragma unroll
                for (int h = 0; h < 2; ++h)
#pragma unroll
                    for (int c = 0; c < 2; ++c) {
                        int rl = wn + ni * 8 + 2 * tig + c;
                        int ii = wm + mi * 16 + grp + 8 * h;
                        Sh[rl * SPH + ii] = __float2half_rn(acc[mi][ni][2 * h + c]);
                    }
        __syncthreads();
#pragma unroll
        for (int it = 0; it < 16; ++it) {
            int idx = it * 256 + tid;
            int rl = idx >> 5, i4 = (idx & 31) * 4;
            uint2 v = *(uint2*)(Sh + rl * SPH + i4);
            *(uint2*)(Oh + (size_t)(2 * (rC + rl) + P) * DCT_N + iC + i4) = v;
        }
    } else {
        float* Sf = (float*)smem;
#pragma unroll 1
        for (int cb = 0; cb < 2; ++cb) {
            if ((wn >> 6) == cb) {
#pragma unroll
                for (int mi = 0; mi < 4; ++mi)
#pragma unroll
                    for (int ni = 0; ni < 4; ++ni)
#pragma unroll
                        for (int h = 0; h < 2; ++h)
#pragma unroll
                            for (int c = 0; c < 2; ++c) {
                                int rl = wn - cb * 64 + ni * 8 + 2 * tig + c;
                                int ii = wm + mi * 16 + grp + 8 * h;
                                Sf[rl * SPF + ii] = acc[mi][ni][2 * h + c];
                            }
            }
            __syncthreads();
#pragma unroll
            for (int it = 0; it < 8; ++it) {
                int idx = it * 256 + tid;
                int rl = idx >> 5, i4 = (idx & 31) * 4;
                int prow = 2 * (rC + cb * 64 + rl) + P;
                float4 v = *(float4*)(Sf + rl * SPF + i4);
                float sc = (2.0f / 512.0f) * (prow == 0 ? is2 : 1.0f);
                v.x *= sc; v.y *= sc; v.z *= sc; v.w *= sc;
                if (iC + i4 == 0) v.x *= is2;
                *(float4*)(Of + (size_t)prow * DCT_N + iC + i4) = v;
            }
            __syncthreads();
        }
    }
}

extern "C" void kernel_launch(void* const* d_in, const int* in_sizes, int n_in,
                              void* d_out, int out_size)
{
    const float* img = (const float*)d_in[0];
    float* out = (float*)d_out;

    init_tables_kernel<<<(KH * KH + 255) / 256, 256>>>();

    dim3 grid(KH / BN, DCT_N / BM, BATCH * 2);   // (2, 4, 256)
    dct_fold_fp16<0><<<grid, 256>>>(img, out);
    dct_fold_fp16<1><<<grid, 256>>>(img, out);
}

// round 6
// speedup vs baseline: 8.8205x; 1.0144x over previous
#include <cuda_runtime.h>
#include <cuda_fp16.h>
#include <cstdint>

// ---------------------------------------------------------------------------
// 2D DCT-II, parity-folded, fp16 mma.sync (m16n8k16, fp32 accum).
// Pass A (MODE 0): T[2r+P][i] = sum_n fold_P(X[i])[n]*tblP[n][r]; epilogue
//   emits prefolded U0[s][j]=T[s][j]+T[s][511-j], U1[s][j]=T[s][j]-T[s][511-j]
//   (CTA tile covers column pairs (j, 511-j)).
// Pass B (MODE 1): Y[2r+P'][s] = scale * sum_j U_{P'}[s][j]*tblP'[j][r].
// ---------------------------------------------------------------------------

#define DCT_N 512
#define BATCH 128
#define KH    256
#define BM    128
#define BN    128
#define BK    64
#define NT    (KH / BK)      // 4
#define APH   72             // A smem pitch (halfs)
#define BPH   136            // B smem pitch (halfs)
#define SPF   132            // epilogue staging pitch (floats)

#define OFF_A0 0
#define OFF_A1 18432
#define OFF_B0 36864
#define OFF_B1 54272
#define SMEM_BYTES 71680     // also covers 128x132 fp32 staging (67584)

__device__ __align__(16) __half g_BE[KH * KH];   // [k'][r] cos(pi(2k'+1)(2r)/1024)
__device__ __align__(16) __half g_BO[KH * KH];   // [k'][r] cos(pi(2k'+1)(2r+1)/1024)
__device__ __align__(16) __half g_U[(size_t)2 * BATCH * DCT_N * KH];  // [P'][b][s][j]

__global__ void init_tables_kernel() {
    int idx = blockIdx.x * blockDim.x + threadIdx.x;
    if (idx >= KH * KH) return;
    int k = idx >> 8, r = idx & 255;
    float a = 2.0f * (float)k + 1.0f;
    g_BE[idx] = __float2half_rn(cospif(a * (float)r * (1.0f / 512.0f)));
    g_BO[idx] = __float2half_rn(cospif(a * (float)(2 * r + 1) * (1.0f / 1024.0f)));
}

__device__ __forceinline__ uint32_t smem_u32(const void* p) {
    uint32_t a;
    asm("{ .reg .u64 t; cvta.to.shared.u64 t, %1; cvt.u32.u64 %0, t; }" : "=r"(a) : "l"(p));
    return a;
}
__device__ __forceinline__ void cp16(uint32_t dst, const void* src) {
    asm volatile("cp.async.cg.shared.global [%0], [%1], 16;" :: "r"(dst), "l"(src));
}
#define CP_COMMIT() asm volatile("cp.async.commit_group;" ::: "memory")
#define CP_WAIT0()  asm volatile("cp.async.wait_group 0;" ::: "memory")

__device__ __forceinline__ void ldsm4(uint32_t r[4], uint32_t addr) {
    asm volatile("ldmatrix.sync.aligned.m8n8.x4.shared.b16 {%0,%1,%2,%3}, [%4];"
                 : "=r"(r[0]), "=r"(r[1]), "=r"(r[2]), "=r"(r[3]) : "r"(addr));
}
__device__ __forceinline__ void ldsm4t(uint32_t r[4], uint32_t addr) {
    asm volatile("ldmatrix.sync.aligned.m8n8.x4.trans.shared.b16 {%0,%1,%2,%3}, [%4];"
                 : "=r"(r[0]), "=r"(r[1]), "=r"(r[2]), "=r"(r[3]) : "r"(addr));
}
__device__ __forceinline__ void mma_f16(float c[4], const uint32_t a[4],
                                        uint32_t b0, uint32_t b1) {
    asm volatile(
        "mma.sync.aligned.m16n8k16.row.col.f32.f16.f16.f32 "
        "{%0,%1,%2,%3},{%4,%5,%6,%7},{%8,%9},{%0,%1,%2,%3};"
        : "+f"(c[0]), "+f"(c[1]), "+f"(c[2]), "+f"(c[3])
        : "r"(a[0]), "r"(a[1]), "r"(a[2]), "r"(a[3]), "r"(b0), "r"(b1));
}
__device__ __forceinline__ uint32_t packh2(float lo, float hi) {
    __half2 h = __floats2half2_rn(lo, hi);
    return *(uint32_t*)&h;
}

// MODE 0: A = img rows (paired i-blocks), out = g_U (prefolded fp16)
// MODE 1: A = g_U[P], out = d_out (fp32, scaled)
template <int MODE>
__global__ __launch_bounds__(256, 2)
void dct_fold_fp16(const float* __restrict__ img, float* __restrict__ out)
{
    extern __shared__ __align__(16) char smem[];
    const uint32_t sb = smem_u32(smem);
    float* Sf = (float*)smem;

    const int tid = threadIdx.x, lane = tid & 31, warp = tid >> 5;
    const int zc = blockIdx.z, bat = zc >> 1, P = zc & 1;
    const float sgn = P ? -1.0f : 1.0f;
    const int yb = blockIdx.y;              // MODE0: j-pair block; MODE1: s block
    const int rC = blockIdx.x * BN;
    const int wm = (warp & 1) * 64, wn = (warp >> 1) * 32;
    const int grp = lane >> 2, tig = lane & 3;

    const __half* tbl = P ? g_BO : g_BE;
    const size_t ustride = (size_t)DCT_N * KH;
    const float* Ef = img + (size_t)bat * DCT_N * DCT_N;
    const __half* Ua = g_U + ((size_t)P * BATCH + bat) * ustride;
    float* Of = out + (size_t)bat * DCT_N * DCT_N;

    // fragment lane byte offsets
    const int aLaneOff =
        ((wm + (lane & 7) + ((lane >> 3) & 1) * 8) * APH + (lane >> 4) * 8) * 2;
    const int bLaneOff =
        (((((lane >> 4) & 1) * 8) + (lane & 7)) * BPH + ((lane >> 3) & 1) * 8) * 2;

    float acc[4][4][4];
#pragma unroll
    for (int mi = 0; mi < 4; ++mi)
#pragma unroll
        for (int ni = 0; ni < 4; ++ni)
#pragma unroll
            for (int r = 0; r < 4; ++r) acc[mi][ni][r] = 0.0f;

    // A-loader coords: 128 rows x 8 granules(8h) -> 4 per thread
    int rowA[4], khh[4];
    const float* rowPtr[4];
#pragma unroll
    for (int i = 0; i < 4; ++i) {
        int g = tid + i * 256;
        rowA[i] = g >> 3;
        khh[i] = (g & 7) * 8;
        if (MODE == 0) {
            int l = rowA[i];
            int gi = (l < 64) ? (64 * yb + l) : (511 - 64 * yb - (l - 64));
            rowPtr[i] = Ef + (size_t)gi * DCT_N;
        }
    }
    // B-loader coords: 64 rows x 16 granules -> 4 per thread
    int rowB[4], nB[4];
#pragma unroll
    for (int i = 0; i < 4; ++i) {
        int g = tid + i * 256;
        rowB[i] = g >> 4;
        nB[i] = (g & 15) * 8;
    }

    uint4 oReg[4];
    auto ldA = [&](int t) {     // MODE 0: fold img -> regs
#pragma unroll
        for (int i = 0; i < 4; ++i) {
            int kp = t * BK + khh[i];
            const float* base = rowPtr[i];
            float4 F0 = *(const float4*)(base + kp);
            float4 F1 = *(const float4*)(base + kp + 4);
            float4 R1 = *(const float4*)(base + 508 - kp);
            float4 R0 = *(const float4*)(base + 504 - kp);
            oReg[i].x = packh2(fmaf(sgn, R1.w, F0.x), fmaf(sgn, R1.z, F0.y));
            oReg[i].y = packh2(fmaf(sgn, R1.y, F0.z), fmaf(sgn, R1.x, F0.w));
            oReg[i].z = packh2(fmaf(sgn, R0.w, F1.x), fmaf(sgn, R0.z, F1.y));
            oReg[i].w = packh2(fmaf(sgn, R0.y, F1.z), fmaf(sgn, R0.x, F1.w));
        }
    };
    auto stsA = [&](int off) {
#pragma unroll
        for (int i = 0; i < 4; ++i)
            *(uint4*)(smem + off + (rowA[i] * APH + khh[i]) * 2) = oReg[i];
    };
    auto cpA = [&](int t, int off) {   // MODE 1: U rows, plain async
#pragma unroll
        for (int i = 0; i < 4; ++i) {
            uint32_t dst = sb + off + (rowA[i] * APH + khh[i]) * 2;
            const __half* src = Ua + (size_t)(yb * BM + rowA[i]) * KH + t * BK + khh[i];
            cp16(dst, src);
        }
    };
    auto cpB = [&](int t, int off) {
#pragma unroll
        for (int i = 0; i < 4; ++i) {
            uint32_t dst = sb + off + (rowB[i] * BPH + nB[i]) * 2;
            const __half* src = tbl + (size_t)(t * BK + rowB[i]) * KH + rC + nB[i];
            cp16(dst, src);
        }
    };
    auto compute = [&](int aOff, int bOff) {
#pragma unroll
        for (int ks = 0; ks < 4; ++ks) {
            uint32_t a[4][4];
#pragma unroll
            for (int mi = 0; mi < 4; ++mi)
                ldsm4(a[mi], sb + aOff + aLaneOff + mi * (16 * APH * 2) + ks * 32);
            uint32_t bq[2][4];
#pragma unroll
            for (int pr = 0; pr < 2; ++pr)
                ldsm4t(bq[pr], sb + bOff + bLaneOff + ks * (16 * BPH * 2)
                               + (wn + pr * 16) * 2);
#pragma unroll
            for (int mi = 0; mi < 4; ++mi)
#pragma unroll
                for (int ni = 0; ni < 4; ++ni)
                    mma_f16(acc[mi][ni], a[mi],
                            bq[ni >> 1][ni & 1], bq[ni >> 1][2 + (ni & 1)]);
        }
    };

    const int aOffs[2] = { OFF_A0, OFF_A1 };
    const int bOffs[2] = { OFF_B0, OFF_B1 };

    // ---- prologue: chunk 0 ----
    if (MODE == 0) { ldA(0); stsA(aOffs[0]); }
    else           { cpA(0, aOffs[0]); }
    cpB(0, bOffs[0]);
    CP_COMMIT();
    if (MODE == 0) ldA(1);
    CP_WAIT0();
    __syncthreads();

    // ---- mainloop: one sync per iteration ----
#pragma unroll 1
    for (int t = 0; t < NT; ++t) {
        if (t + 1 < NT) {
            if (MODE == 0) stsA(aOffs[(t + 1) & 1]);
            else           cpA(t + 1, aOffs[(t + 1) & 1]);
            cpB(t + 1, bOffs[(t + 1) & 1]);
            CP_COMMIT();
            if (MODE == 0 && t + 2 < NT) ldA(t + 2);
        }
        compute(aOffs[t & 1], bOffs[t & 1]);
        if (t + 1 < NT) {
            CP_WAIT0();
            __syncthreads();
        }
    }
    __syncthreads();

    // ---- epilogue: stage full 128x128 fp32 tile ----
#pragma unroll
    for (int mi = 0; mi < 4; ++mi)
#pragma unroll
        for (int ni = 0; ni < 4; ++ni)
#pragma unroll
            for (int h = 0; h < 2; ++h)
#pragma unroll
                for (int c = 0; c < 2; ++c) {
                    int rl = wn + ni * 8 + 2 * tig + c;
                    int ii = wm + mi * 16 + grp + 8 * h;
                    Sf[rl * SPF + ii] = acc[mi][ni][2 * h + c];
                }
    __syncthreads();

    const float is2 = 0.70710678118654752440f;
    if (MODE == 0) {
        __half* U0 = g_U + (size_t)bat * ustride;
        __half* U1 = g_U + ((size_t)BATCH + bat) * ustride;
#pragma unroll
        for (int it = 0; it < 8; ++it) {
            int idx = it * 256 + tid;
            int rl = idx >> 4, l4 = (idx & 15) * 4;
            float4 a = *(float4*)(Sf + rl * SPF + l4);
            float4 b = *(float4*)(Sf + rl * SPF + l4 + 64);
            uint2 p0, p1;
            p0.x = packh2(a.x + b.x, a.y + b.y);
            p0.y = packh2(a.z + b.z, a.w + b.w);
            p1.x = packh2(a.x - b.x, a.y - b.y);
            p1.y = packh2(a.z - b.z, a.w - b.w);
            size_t off = (size_t)(2 * (rC + rl) + P) * KH + 64 * yb + l4;
            *(uint2*)(U0 + off) = p0;
            *(uint2*)(U1 + off) = p1;
        }
    } else {
#pragma unroll
        for (int it = 0; it < 16; ++it) {
            int idx = it * 256 + tid;
            int rl = idx >> 5, i4 = (idx & 31) * 4;
            int prow = 2 * (rC + rl) + P;
            float4 v = *(float4*)(Sf + rl * SPF + i4);
            float sc = (2.0f / 512.0f) * (prow == 0 ? is2 : 1.0f);
            v.x *= sc; v.y *= sc; v.z *= sc; v.w *= sc;
            if (yb * BM + i4 == 0) v.x *= is2;
            *(float4*)(Of + (size_t)prow * DCT_N + yb * BM + i4) = v;
        }
    }
}

extern "C" void kernel_launch(void* const* d_in, const int* in_sizes, int n_in,
                              void* d_out, int out_size)
{
    const float* img = (const float*)d_in[0];
    float* out = (float*)d_out;

    static bool attr_set = false;
    if (!attr_set) {
        cudaFuncSetAttribute(dct_fold_fp16<0>,
                             cudaFuncAttributeMaxDynamicSharedMemorySize, SMEM_BYTES);
        cudaFuncSetAttribute(dct_fold_fp16<1>,
                             cudaFuncAttributeMaxDynamicSharedMemorySize, SMEM_BYTES);
        attr_set = true;
    }

    init_tables_kernel<<<(KH * KH + 255) / 256, 256>>>();

    dim3 grid(KH / BN, 4, BATCH * 2);   // (2, 4, 256)
    dct_fold_fp16<0><<<grid, 256, SMEM_BYTES>>>(img, out);
    dct_fold_fp16<1><<<grid, 256, SMEM_BYTES>>>(img, out);
}

// round 7
// speedup vs baseline: 9.4564x; 1.0721x over previous
#include <cuda_runtime.h>
#include <cuda_fp16.h>
#include <cstdint>

// ---------------------------------------------------------------------------
// 2D DCT-II, two-level parity folding, fp16 mma.sync (m16n8k16, fp32 accum).
// Output rows split into 3 branches per pass:
//   q odd     : K=256, input u1  = x[n]-x[511-n],          tbl cos(pi(2n+1)(2r+1)/1024)
//   q = 4s    : K=128, input u00 = (x[n]+x[511-n])+(x[255-n]+x[256+n]), tbl cos(pi(2n+1)s/256)
//   q = 4s+2  : K=128, input u01 = (x[n]+x[511-n])-(x[255-n]+x[256+n]), tbl cos(pi(2n+1)(2s+1)/512)
// Pass A emits prefolded (along i) U0/U1 in fp16; pass B folds U0 again in
// its loader for the even branches.
// ---------------------------------------------------------------------------

#define DCT_N 512
#define BATCH 128
#define KH    256
#define BM    128
#define BN    128
#define BK    64
#define APH   72             // A smem pitch (halfs)
#define BPH   136            // B smem pitch (halfs)
#define SPF   132            // epilogue staging pitch (floats)

#define OFF_A0 0
#define OFF_A1 18432
#define OFF_B0 36864
#define OFF_B1 54272
#define SMEM_BYTES 71680

__device__ __align__(16) __half g_T1 [KH * KH];     // [n][r] cos(pi(2n+1)(2r+1)/1024)
__device__ __align__(16) __half g_TEE[128 * 128];   // [n][s] cos(pi(2n+1)s/256)
__device__ __align__(16) __half g_TEO[128 * 128];   // [n][s] cos(pi(2n+1)(2s+1)/512)
__device__ __align__(16) __half g_U[(size_t)2 * BATCH * DCT_N * KH];  // [lvl1 parity][b][q][j]

__global__ void init_tables_kernel() {
    int idx = blockIdx.x * blockDim.x + threadIdx.x;
    if (idx < KH * KH) {
        int n = idx >> 8, r = idx & 255;
        g_T1[idx] = __float2half_rn(
            cospif((2.0f * n + 1.0f) * (2.0f * r + 1.0f) * (1.0f / 1024.0f)));
    } else if (idx < KH * KH + 128 * 128) {
        int j = idx - KH * KH;
        int n = j >> 7, s = j & 127;
        g_TEE[j] = __float2half_rn(
            cospif((2.0f * n + 1.0f) * (float)s * (1.0f / 256.0f)));
    } else if (idx < KH * KH + 2 * 128 * 128) {
        int j = idx - KH * KH - 128 * 128;
        int n = j >> 7, s = j & 127;
        g_TEO[j] = __float2half_rn(
            cospif((2.0f * n + 1.0f) * (2.0f * s + 1.0f) * (1.0f / 512.0f)));
    }
}

__device__ __forceinline__ uint32_t smem_u32(const void* p) {
    uint32_t a;
    asm("{ .reg .u64 t; cvta.to.shared.u64 t, %1; cvt.u32.u64 %0, t; }" : "=r"(a) : "l"(p));
    return a;
}
__device__ __forceinline__ void cp16(uint32_t dst, const void* src) {
    asm volatile("cp.async.cg.shared.global [%0], [%1], 16;" :: "r"(dst), "l"(src));
}
#define CP_COMMIT() asm volatile("cp.async.commit_group;" ::: "memory")
#define CP_WAIT0()  asm volatile("cp.async.wait_group 0;" ::: "memory")

__device__ __forceinline__ void ldsm4(uint32_t r[4], uint32_t addr) {
    asm volatile("ldmatrix.sync.aligned.m8n8.x4.shared.b16 {%0,%1,%2,%3}, [%4];"
                 : "=r"(r[0]), "=r"(r[1]), "=r"(r[2]), "=r"(r[3]) : "r"(addr));
}
__device__ __forceinline__ void ldsm4t(uint32_t r[4], uint32_t addr) {
    asm volatile("ldmatrix.sync.aligned.m8n8.x4.trans.shared.b16 {%0,%1,%2,%3}, [%4];"
                 : "=r"(r[0]), "=r"(r[1]), "=r"(r[2]), "=r"(r[3]) : "r"(addr));
}
__device__ __forceinline__ void mma_f16(float c[4], const uint32_t a[4],
                                        uint32_t b0, uint32_t b1) {
    asm volatile(
        "mma.sync.aligned.m16n8k16.row.col.f32.f16.f16.f32 "
        "{%0,%1,%2,%3},{%4,%5,%6,%7},{%8,%9},{%0,%1,%2,%3};"
        : "+f"(c[0]), "+f"(c[1]), "+f"(c[2]), "+f"(c[3])
        : "r"(a[0]), "r"(a[1]), "r"(a[2]), "r"(a[3]), "r"(b0), "r"(b1));
}
__device__ __forceinline__ uint32_t packh2(float lo, float hi) {
    __half2 h = __floats2half2_rn(lo, hi);
    return *(uint32_t*)&h;
}

// MODE 0: A-source = img (fp32, folded inline), out = g_U (prefolded fp16)
// MODE 1: A-source = g_U (odd: U1 async; even: fold of U0), out = d_out
template <int MODE>
__global__ __launch_bounds__(256, 2)
void dct_fold_fp16(const float* __restrict__ img, float* __restrict__ out)
{
    extern __shared__ __align__(16) char smem[];
    const uint32_t sb = smem_u32(smem);
    float* Sf = (float*)smem;

    const int tid = threadIdx.x, lane = tid & 31, warp = tid >> 5;
    const int jx  = blockIdx.x;          // 0,1: odd-q blocks; 2: q=4s; 3: q=4s+2
    const int bat = blockIdx.z;
    const int yb  = blockIdx.y;
    const bool ODD = (jx < 2);
    const int  NT  = ODD ? 4 : 2;        // K / BK
    const int  rC  = ODD ? jx * BN : 0;
    const int  TW  = ODD ? KH : 128;     // table row width
    const __half* tbl = ODD ? g_T1 : (jx == 2 ? g_TEE : g_TEO);
    const float sg2 = (jx == 3) ? -1.0f : 1.0f;
    const int wm = (warp & 1) * 64, wn = (warp >> 1) * 32;
    const int grp = lane >> 2, tig = lane & 3;

    const size_t ustride = (size_t)DCT_N * KH;
    const float* Ef  = img + (size_t)bat * DCT_N * DCT_N;
    const __half* U0a = g_U + (size_t)bat * ustride;
    const __half* U1a = g_U + ((size_t)BATCH + bat) * ustride;
    float* Of = out + (size_t)bat * DCT_N * DCT_N;

    const int aLaneOff =
        ((wm + (lane & 7) + ((lane >> 3) & 1) * 8) * APH + (lane >> 4) * 8) * 2;
    const int bLaneOff =
        (((((lane >> 4) & 1) * 8) + (lane & 7)) * BPH + ((lane >> 3) & 1) * 8) * 2;

    float acc[4][4][4];
#pragma unroll
    for (int mi = 0; mi < 4; ++mi)
#pragma unroll
        for (int ni = 0; ni < 4; ++ni)
#pragma unroll
            for (int r = 0; r < 4; ++r) acc[mi][ni][r] = 0.0f;

    // A-loader coords: 128 rows x 8 granules(8h) -> 4 per thread
    int rowA[4], khh[4];
    const float*  rowPtr[4];   // MODE 0
    const __half* u0Ptr[4];    // MODE 1 even
#pragma unroll
    for (int i = 0; i < 4; ++i) {
        int g = tid + i * 256;
        rowA[i] = g >> 3;
        khh[i] = (g & 7) * 8;
        if (MODE == 0) {
            int l = rowA[i];
            int gi = (l < 64) ? (64 * yb + l) : (511 - 64 * yb - (l - 64));
            rowPtr[i] = Ef + (size_t)gi * DCT_N;
        } else {
            u0Ptr[i] = U0a + (size_t)(yb * BM + rowA[i]) * KH;
        }
    }
    // B-loader coords: 64 rows x 16 granules -> 4 per thread
    int rowB[4], nB[4];
#pragma unroll
    for (int i = 0; i < 4; ++i) {
        int g = tid + i * 256;
        rowB[i] = g >> 4;
        nB[i] = (g & 15) * 8;
    }

    uint4 oReg[4];
    auto ldA = [&](int t) {
#pragma unroll
        for (int i = 0; i < 4; ++i) {
            int kp = t * BK + khh[i];
            if (MODE == 0) {
                const float* base = rowPtr[i];
                float4 F0 = *(const float4*)(base + kp);
                float4 F1 = *(const float4*)(base + kp + 4);
                float4 R1 = *(const float4*)(base + 508 - kp);
                float4 R0 = *(const float4*)(base + 504 - kp);
                if (ODD) {
                    oReg[i].x = packh2(F0.x - R1.w, F0.y - R1.z);
                    oReg[i].y = packh2(F0.z - R1.y, F0.w - R1.x);
                    oReg[i].z = packh2(F1.x - R0.w, F1.y - R0.z);
                    oReg[i].w = packh2(F1.z - R0.y, F1.w - R0.x);
                } else {
                    float4 C1 = *(const float4*)(base + 252 - kp);
                    float4 C0 = *(const float4*)(base + 248 - kp);
                    float4 D0 = *(const float4*)(base + 256 + kp);
                    float4 D1 = *(const float4*)(base + 260 + kp);
                    oReg[i].x = packh2(fmaf(sg2, C1.w + D0.x, F0.x + R1.w),
                                       fmaf(sg2, C1.z + D0.y, F0.y + R1.z));
                    oReg[i].y = packh2(fmaf(sg2, C1.y + D0.z, F0.z + R1.y),
                                       fmaf(sg2, C1.x + D0.w, F0.w + R1.x));
                    oReg[i].z = packh2(fmaf(sg2, C0.w + D1.x, F1.x + R0.w),
                                       fmaf(sg2, C0.z + D1.y, F1.y + R0.z));
                    oReg[i].w = packh2(fmaf(sg2, C0.y + D1.z, F1.z + R0.y),
                                       fmaf(sg2, C0.x + D1.w, F1.w + R0.x));
                }
            } else {  // MODE 1 even branches: fp16 fold of U0
                const __half* base = u0Ptr[i];
                uint4 F = *(const uint4*)(base + kp);
                uint4 R = *(const uint4*)(base + 248 - kp);
                __half2 f0 = *(__half2*)&F.x, f1 = *(__half2*)&F.y;
                __half2 f2 = *(__half2*)&F.z, f3 = *(__half2*)&F.w;
                __half2 r0 = __lowhigh2highlow(*(__half2*)&R.w);
                __half2 r1 = __lowhigh2highlow(*(__half2*)&R.z);
                __half2 r2 = __lowhigh2highlow(*(__half2*)&R.y);
                __half2 r3 = __lowhigh2highlow(*(__half2*)&R.x);
                __half2 o0, o1, o2, o3;
                if (jx == 2) {
                    o0 = __hadd2(f0, r0); o1 = __hadd2(f1, r1);
                    o2 = __hadd2(f2, r2); o3 = __hadd2(f3, r3);
                } else {
                    o0 = __hsub2(f0, r0); o1 = __hsub2(f1, r1);
                    o2 = __hsub2(f2, r2); o3 = __hsub2(f3, r3);
                }
                oReg[i].x = *(uint32_t*)&o0; oReg[i].y = *(uint32_t*)&o1;
                oReg[i].z = *(uint32_t*)&o2; oReg[i].w = *(uint32_t*)&o3;
            }
        }
    };
    auto stsA = [&](int off) {
#pragma unroll
        for (int i = 0; i < 4; ++i)
            *(uint4*)(smem + off + (rowA[i] * APH + khh[i]) * 2) = oReg[i];
    };
    auto cpA = [&](int t, int off) {   // MODE 1 odd: U1 rows, pure async
#pragma unroll
        for (int i = 0; i < 4; ++i) {
            uint32_t dst = sb + off + (rowA[i] * APH + khh[i]) * 2;
            const __half* src = U1a + (size_t)(yb * BM + rowA[i]) * KH + t * BK + khh[i];
            cp16(dst, src);
        }
    };
    auto cpB = [&](int t, int off) {
#pragma unroll
        for (int i = 0; i < 4; ++i) {
            uint32_t dst = sb + off + (rowB[i] * BPH + nB[i]) * 2;
            const __half* src = tbl + (size_t)(t * BK + rowB[i]) * TW + rC + nB[i];
            cp16(dst, src);
        }
    };
    auto compute = [&](int aOff, int bOff) {
#pragma unroll
        for (int ks = 0; ks < 4; ++ks) {
            uint32_t a[4][4];
#pragma unroll
            for (int mi = 0; mi < 4; ++mi)
                ldsm4(a[mi], sb + aOff + aLaneOff + mi * (16 * APH * 2) + ks * 32);
            uint32_t bq[2][4];
#pragma unroll
            for (int pr = 0; pr < 2; ++pr)
                ldsm4t(bq[pr], sb + bOff + bLaneOff + ks * (16 * BPH * 2)
                               + (wn + pr * 16) * 2);
#pragma unroll
            for (int mi = 0; mi < 4; ++mi)
#pragma unroll
                for (int ni = 0; ni < 4; ++ni)
                    mma_f16(acc[mi][ni], a[mi],
                            bq[ni >> 1][ni & 1], bq[ni >> 1][2 + (ni & 1)]);
        }
    };

    const int aOffs[2] = { OFF_A0, OFF_A1 };
    const int bOffs[2] = { OFF_B0, OFF_B1 };
    const bool regpath = (MODE == 0) || !ODD;

    // ---- prologue ----
    if (regpath) { ldA(0); stsA(aOffs[0]); }
    else         { cpA(0, aOffs[0]); }
    cpB(0, bOffs[0]);
    CP_COMMIT();
    if (regpath) ldA(1);
    CP_WAIT0();
    __syncthreads();

    // ---- mainloop ----
#pragma unroll 1
    for (int t = 0; t < NT; ++t) {
        if (t + 1 < NT) {
            if (regpath) stsA(aOffs[(t + 1) & 1]);
            else         cpA(t + 1, aOffs[(t + 1) & 1]);
            cpB(t + 1, bOffs[(t + 1) & 1]);
            CP_COMMIT();
            if (regpath && t + 2 < NT) ldA(t + 2);
        }
        compute(aOffs[t & 1], bOffs[t & 1]);
        if (t + 1 < NT) {
            CP_WAIT0();
            __syncthreads();
        }
    }
    __syncthreads();

    // ---- epilogue: stage full 128x128 fp32 tile ----
#pragma unroll
    for (int mi = 0; mi < 4; ++mi)
#pragma unroll
        for (int ni = 0; ni < 4; ++ni)
#pragma unroll
            for (int h = 0; h < 2; ++h)
#pragma unroll
                for (int c = 0; c < 2; ++c) {
                    int rl = wn + ni * 8 + 2 * tig + c;
                    int ii = wm + mi * 16 + grp + 8 * h;
                    Sf[rl * SPF + ii] = acc[mi][ni][2 * h + c];
                }
    __syncthreads();

    const float is2 = 0.70710678118654752440f;
    if (MODE == 0) {
        __half* U0w = g_U + (size_t)bat * ustride;
        __half* U1w = g_U + ((size_t)BATCH + bat) * ustride;
#pragma unroll
        for (int it = 0; it < 8; ++it) {
            int idx = it * 256 + tid;
            int rl = idx >> 4, l4 = (idx & 15) * 4;
            int q = ODD ? (2 * (rC + rl) + 1) : (jx == 2 ? 4 * rl : 4 * rl + 2);
            float4 a = *(float4*)(Sf + rl * SPF + l4);
            float4 b = *(float4*)(Sf + rl * SPF + l4 + 64);
            uint2 p0, p1;
            p0.x = packh2(a.x + b.x, a.y + b.y);
            p0.y = packh2(a.z + b.z, a.w + b.w);
            p1.x = packh2(a.x - b.x, a.y - b.y);
            p1.y = packh2(a.z - b.z, a.w - b.w);
            size_t off = (size_t)q * KH + 64 * yb + l4;
            *(uint2*)(U0w + off) = p0;
            *(uint2*)(U1w + off) = p1;
        }
    } else {
#pragma unroll
        for (int it = 0; it < 16; ++it) {
            int idx = it * 256 + tid;
            int rl = idx >> 5, i4 = (idx & 31) * 4;
            int prow = ODD ? (2 * (rC + rl) + 1) : (jx == 2 ? 4 * rl : 4 * rl + 2);
            float4 v = *(float4*)(Sf + rl * SPF + i4);
            float sc = (2.0f / 512.0f) * (prow == 0 ? is2 : 1.0f);
            v.x *= sc; v.y *= sc; v.z *= sc; v.w *= sc;
            if (yb * BM + i4 == 0) v.x *= is2;
            *(float4*)(Of + (size_t)prow * DCT_N + yb * BM + i4) = v;
        }
    }
}

extern "C" void kernel_launch(void* const* d_in, const int* in_sizes, int n_in,
                              void* d_out, int out_size)
{
    const float* img = (const float*)d_in[0];
    float* out = (float*)d_out;

    static bool attr_set = false;
    if (!attr_set) {
        cudaFuncSetAttribute(dct_fold_fp16<0>,
                             cudaFuncAttributeMaxDynamicSharedMemorySize, SMEM_BYTES);
        cudaFuncSetAttribute(dct_fold_fp16<1>,
                             cudaFuncAttributeMaxDynamicSharedMemorySize, SMEM_BYTES);
        attr_set = true;
    }

    const int tbl_elems = KH * KH + 2 * 128 * 128;   // 98304
    init_tables_kernel<<<(tbl_elems + 255) / 256, 256>>>();

    dim3 grid(4, 4, BATCH);   // jx: {odd0, odd1, ee, eo}
    dct_fold_fp16<0><<<grid, 256, SMEM_BYTES>>>(img, out);
    dct_fold_fp16<1><<<grid, 256, SMEM_BYTES>>>(img, out);
}